// round 13
// baseline (speedup 1.0000x reference)
#include <cuda_runtime.h>
#include <math.h>
#include <stdint.h>

#define DMODEL 1024
#define NHEAD  16
#define HDIM   64
#define DFF    2730
#define DHALT  256
#define BATCH  2
#define SEQ    2048
#define NROWS  (BATCH*SEQ)   // 4096
#define NQT    (SEQ/64)      // 32 q-tiles per (b,h)

// ---------------- scratch (static device globals: allocation-guard safe) ---------
__device__ float g_h1[(size_t)NROWS*DMODEL];
__device__ float g_qkv[(size_t)NROWS*3*DMODEL];
__device__ float g_attn[(size_t)NROWS*DMODEL];
__device__ float g_x1[(size_t)NROWS*DMODEL];
__device__ float g_h2[(size_t)NROWS*DMODEL];
__device__ float g_u[(size_t)NROWS*DFF];
__device__ float g_v[(size_t)NROWS*DFF];
__device__ float g_hh[(size_t)NROWS*DHALT];

// ---------------- rmsnorm: one block per row --------------------------------
__global__ void rmsnorm_kernel(const float* __restrict__ x, const float* __restrict__ g,
                               float* __restrict__ y) {
    int row = blockIdx.x;
    const float* xr = x + (size_t)row * DMODEL;
    int t = threadIdx.x;
    float v[4];
    float ss = 0.f;
#pragma unroll
    for (int i = 0; i < 4; i++) { v[i] = xr[t + i * 256]; ss += v[i] * v[i]; }
    for (int off = 16; off; off >>= 1) ss += __shfl_xor_sync(0xffffffffu, ss, off);
    __shared__ float red[8];
    if ((t & 31) == 0) red[t >> 5] = ss;
    __syncthreads();
    if (t < 8) {
        float s2 = red[t];
        for (int off = 4; off; off >>= 1) s2 += __shfl_xor_sync(0xffu, s2, off);
        if (t == 0) red[0] = s2;
    }
    __syncthreads();
    float inv = rsqrtf(red[0] * (1.0f / DMODEL) + 1e-6f);
    float* yr = y + (size_t)row * DMODEL;
#pragma unroll
    for (int i = 0; i < 4; i++) {
        int c = t + i * 256;
        yr[c] = v[i] * inv * g[c];
    }
}

// ---------------- async-copy + mma helpers -----------------------------------
__device__ __forceinline__ uint32_t s2u(const void* p) {
    return (uint32_t)__cvta_generic_to_shared(p);
}
__device__ __forceinline__ void cp16(uint32_t d, const void* s) {
    asm volatile("cp.async.cg.shared.global [%0], [%1], 16;" :: "r"(d), "l"(s));
}
__device__ __forceinline__ void cp4(uint32_t d, const void* s) {
    asm volatile("cp.async.ca.shared.global [%0], [%1], 4;" :: "r"(d), "l"(s));
}
__device__ __forceinline__ void cp_commit() {
    asm volatile("cp.async.commit_group;");
}
__device__ __forceinline__ void mma_tf32(float c[4], const uint32_t a[4], const uint32_t b[2]) {
    asm volatile(
        "mma.sync.aligned.m16n8k8.row.col.f32.tf32.tf32.f32 "
        "{%0,%1,%2,%3}, {%4,%5,%6,%7}, {%8,%9}, {%0,%1,%2,%3};"
        : "+f"(c[0]), "+f"(c[1]), "+f"(c[2]), "+f"(c[3])
        : "r"(a[0]), "r"(a[1]), "r"(a[2]), "r"(a[3]), "r"(b[0]), "r"(b[1]));
}
__device__ __forceinline__ float tf32r(float x) {   // round-to-nearest tf32
    uint32_t y;
    asm("cvt.rna.tf32.f32 %0, %1;" : "=r"(y) : "f"(x));
    return __uint_as_float(y);
}

// ---------------- TF32 tensor-core GEMM body (R9 config: measured best) ------
#define AS_STRIDE 36
#define BS_STRIDE 136
#define A_TILE (128 * AS_STRIDE)
#define B_TILE (32 * BS_STRIDE)
#define STAGE  (A_TILE + B_TILE)
#define NSTAGE 3
#define GEMM_SMEM (NSTAGE * STAGE * sizeof(float))   // 107520 B

template <int MODE, int AVEC, int BVEC>
__device__ __forceinline__ void gemm_body(const float* __restrict__ A,
                                          const float* __restrict__ Bm,
                                          float* __restrict__ C,
                                          const float* __restrict__ E,
                                          int M, int K, int N, int m0, int n0,
                                          float* smem) {
    int tid = threadIdx.x;
    int w = tid >> 5, lane = tid & 31;
    int warpM = w >> 2, warpN = w & 3;
    int group = lane >> 2, tig = lane & 3;

    auto load_tile = [&](int k0, int stg) {
        float* sA = smem + stg * STAGE;
        float* sB = sA + A_TILE;
        if (AVEC) {
#pragma unroll
            for (int i = 0; i < 4; i++) {
                int c = i * 256 + tid;
                int m = c >> 3, k4 = (c & 7) * 4;
                float* dp = sA + m * AS_STRIDE + k4;
                const float* sp = A + (size_t)(m0 + m) * K + k0 + k4;
                if (k0 + k4 + 4 <= K) cp16(s2u(dp), sp);
                else {
#pragma unroll
                    for (int e = 0; e < 4; e++) dp[e] = (k0 + k4 + e < K) ? sp[e] : 0.f;
                }
            }
        } else {
#pragma unroll
            for (int i = 0; i < 16; i++) {
                int c = i * 256 + tid;
                int m = c >> 5, kk = c & 31;
                float* dp = sA + m * AS_STRIDE + kk;
                if (k0 + kk < K) cp4(s2u(dp), A + (size_t)(m0 + m) * K + k0 + kk);
                else *dp = 0.f;
            }
        }
        if (BVEC) {
#pragma unroll
            for (int i = 0; i < 4; i++) {
                int c = i * 256 + tid;
                int kk = c >> 5, n4 = (c & 31) * 4;
                float* dp = sB + kk * BS_STRIDE + n4;
                if (k0 + kk < K) cp16(s2u(dp), Bm + (size_t)(k0 + kk) * N + n0 + n4);
                else { dp[0] = 0.f; dp[1] = 0.f; dp[2] = 0.f; dp[3] = 0.f; }
            }
        } else {
#pragma unroll
            for (int i = 0; i < 16; i++) {
                int c = i * 256 + tid;
                int kk = c >> 7, n = c & 127;
                float* dp = sB + kk * BS_STRIDE + n;
                if (k0 + kk < K && n0 + n < N) cp4(s2u(dp), Bm + (size_t)(k0 + kk) * N + n0 + n);
                else *dp = 0.f;
            }
        }
    };

    float acc[4][4][4];
#pragma unroll
    for (int mi = 0; mi < 4; mi++)
#pragma unroll
        for (int ni = 0; ni < 4; ni++)
#pragma unroll
            for (int r = 0; r < 4; r++) acc[mi][ni][r] = 0.f;

    int ntiles = (K + 31) / 32;
    load_tile(0, 0);
    cp_commit();
    if (ntiles > 1) { load_tile(32, 1); cp_commit(); }

    for (int t = 0; t < ntiles; t++) {
        if (t + 1 < ntiles) asm volatile("cp.async.wait_group 1;");
        else                asm volatile("cp.async.wait_group 0;");
        __syncthreads();
        if (t + 2 < ntiles) {
            load_tile((t + 2) * 32, (t + 2) % NSTAGE);
            cp_commit();
        }

        const float* sA = smem + (t % NSTAGE) * STAGE;
        const float* sB = sA + A_TILE;
#pragma unroll
        for (int ks = 0; ks < 32; ks += 8) {
            uint32_t afrag[4][4], bfrag[4][2];
#pragma unroll
            for (int mi = 0; mi < 4; mi++) {
                int rm = warpM * 64 + mi * 16;
                afrag[mi][0] = __float_as_uint(sA[(rm + group)     * AS_STRIDE + ks + tig]);
                afrag[mi][1] = __float_as_uint(sA[(rm + group + 8) * AS_STRIDE + ks + tig]);
                afrag[mi][2] = __float_as_uint(sA[(rm + group)     * AS_STRIDE + ks + tig + 4]);
                afrag[mi][3] = __float_as_uint(sA[(rm + group + 8) * AS_STRIDE + ks + tig + 4]);
            }
#pragma unroll
            for (int ni = 0; ni < 4; ni++) {
                int cn = warpN * 32 + ni * 8;
                bfrag[ni][0] = __float_as_uint(sB[(ks + tig)     * BS_STRIDE + cn + group]);
                bfrag[ni][1] = __float_as_uint(sB[(ks + tig + 4) * BS_STRIDE + cn + group]);
            }
#pragma unroll
            for (int mi = 0; mi < 4; mi++)
#pragma unroll
                for (int ni = 0; ni < 4; ni++)
                    mma_tf32(acc[mi][ni], afrag[mi], bfrag[ni]);
        }
    }

#pragma unroll
    for (int mi = 0; mi < 4; mi++) {
        int row = m0 + warpM * 64 + mi * 16 + group;
#pragma unroll
        for (int ni = 0; ni < 4; ni++) {
            int col = n0 + warpN * 32 + ni * 8 + tig * 2;
            if (col >= N) continue;
            float2 lo = make_float2(acc[mi][ni][0], acc[mi][ni][1]);
            float2 hi = make_float2(acc[mi][ni][2], acc[mi][ni][3]);
            if (MODE == 1) {
                float2 e0 = *(const float2*)&E[(size_t)row * N + col];
                float2 e1 = *(const float2*)&E[(size_t)(row + 8) * N + col];
                lo.x += e0.x; lo.y += e0.y; hi.x += e1.x; hi.y += e1.y;
            }
            if (MODE == 2) {
                float2 bb = *(const float2*)&E[col];
                lo.x += bb.x; lo.y += bb.y; hi.x += bb.x; hi.y += bb.y;
                lo.x = 0.5f * lo.x * (1.f + erff(lo.x * 0.70710678118654752f));
                lo.y = 0.5f * lo.y * (1.f + erff(lo.y * 0.70710678118654752f));
                hi.x = 0.5f * hi.x * (1.f + erff(hi.x * 0.70710678118654752f));
                hi.y = 0.5f * hi.y * (1.f + erff(hi.y * 0.70710678118654752f));
            }
            *(float2*)&C[(size_t)row * N + col] = lo;
            *(float2*)&C[(size_t)(row + 8) * N + col] = hi;
        }
    }
}

template <int MODE, int AVEC, int BVEC>
__global__ void __launch_bounds__(256) gemm_tc(const float* __restrict__ A,
                                               const float* __restrict__ Bm,
                                               float* __restrict__ C,
                                               const float* __restrict__ E,
                                               int M, int K, int N) {
    extern __shared__ float smem[];
    gemm_body<MODE, AVEC, BVEC>(A, Bm, C, E, M, K, N,
                                blockIdx.y * 128, blockIdx.x * 128, smem);
}

// W1 + W2 merged launch (kept: wave-quantization win)
__global__ void __launch_bounds__(256) gemm_w1w2(const float* __restrict__ A,
                                                 const float* __restrict__ B1,
                                                 const float* __restrict__ B2,
                                                 float* __restrict__ C1,
                                                 float* __restrict__ C2,
                                                 int M, int K, int N) {
    extern __shared__ float smem[];
    int ntile = (N + 127) / 128;
    int bx = blockIdx.x;
    if (bx < ntile)
        gemm_body<0, 1, 0>(A, B1, C1, nullptr, M, K, N, blockIdx.y * 128, bx * 128, smem);
    else
        gemm_body<0, 1, 0>(A, B2, C2, nullptr, M, K, N, blockIdx.y * 128, (bx - ntile) * 128, smem);
}

// ---------------- tf32 flash attention: heavy-first single-qtile blocks ------
// grid (NQT, B*H). qtile = NQT-1-blockIdx.x: heaviest blocks issue first (LPT),
// last-issued stragglers are the 1-KV-tile blocks -> short tail.
#define QS_ST 68
#define KT_ST 72
#define VS_ST 72
#define PS_ST 68
#define ATTN_SMEM ((64*QS_ST + 64*KT_ST + 64*VS_ST + 64*PS_ST) * 4)  // 71680 B

__global__ void __launch_bounds__(128) attn_tc(const float* __restrict__ qkv,
                                               float* __restrict__ out) {
    extern __shared__ float sm[];
    float* Qs = sm;
    float* KT = Qs + 64 * QS_ST;
    float* Vs = KT + 64 * KT_ST;
    float* Ps = Vs + 64 * VS_ST;
    int tid = threadIdx.x;
    int warp = tid >> 5, lane = tid & 31;
    int group = lane >> 2, tig = lane & 3;
    int bh = blockIdx.y;
    int b = bh >> 4, h = bh & 15;
    int qtile = NQT - 1 - (int)blockIdx.x;   // heavy-first
    int qt0 = qtile * 64;
    size_t base = (size_t)b * SEQ * 3072;
    int rm = warp * 16;
    int ld_r = tid >> 4, ld_dq = tid & 15;

    // load Q tile (rna-rounded)
#pragma unroll
    for (int i = 0; i < 8; i++) {
        int e = i * 128 + tid;
        int r = e >> 4, dq = e & 15;
        float4 q = *(const float4*)&qkv[base + (size_t)(qt0 + r) * 3072 + h * 64 + dq * 4];
        float* d = &Qs[r * QS_ST + dq * 4];
        d[0] = tf32r(q.x); d[1] = tf32r(q.y); d[2] = tf32r(q.z); d[3] = tf32r(q.w);
    }

    float4 kreg[8], vreg[8];
    auto load_kv = [&](int j0) {
#pragma unroll
        for (int i = 0; i < 8; i++) {
            int r = ld_r + i * 8;
            const float* kp = &qkv[base + (size_t)(j0 + r) * 3072 + 1024 + h * 64 + ld_dq * 4];
            kreg[i] = *(const float4*)kp;
            vreg[i] = *(const float4*)(kp + 1024);
        }
    };

    float o[8][4];
    float m0 = -1e30f, m1 = -1e30f, l0 = 0.f, l1 = 0.f;
#pragma unroll
    for (int ni = 0; ni < 8; ni++)
#pragma unroll
        for (int r = 0; r < 4; r++) o[ni][r] = 0.f;

    int jt_max = qtile;
    load_kv(0);
    for (int jt = 0; jt <= jt_max; jt++) {
        __syncthreads();
#pragma unroll
        for (int i = 0; i < 8; i++) {
            int r = ld_r + i * 8;
            KT[(ld_dq * 4 + 0) * KT_ST + r] = tf32r(kreg[i].x);
            KT[(ld_dq * 4 + 1) * KT_ST + r] = tf32r(kreg[i].y);
            KT[(ld_dq * 4 + 2) * KT_ST + r] = tf32r(kreg[i].z);
            KT[(ld_dq * 4 + 3) * KT_ST + r] = tf32r(kreg[i].w);
            float4 vt;
            vt.x = tf32r(vreg[i].x); vt.y = tf32r(vreg[i].y);
            vt.z = tf32r(vreg[i].z); vt.w = tf32r(vreg[i].w);
            *(float4*)&Vs[r * VS_ST + ld_dq * 4] = vt;
        }
        __syncthreads();
        if (jt < jt_max) load_kv((jt + 1) * 64);

        int j0 = jt * 64;
        float s[8][4];
#pragma unroll
        for (int ni = 0; ni < 8; ni++)
#pragma unroll
            for (int r = 0; r < 4; r++) s[ni][r] = 0.f;
#pragma unroll
        for (int ks = 0; ks < 64; ks += 8) {
            uint32_t a[4];
            a[0] = __float_as_uint(Qs[(rm + group)     * QS_ST + ks + tig]);
            a[1] = __float_as_uint(Qs[(rm + group + 8) * QS_ST + ks + tig]);
            a[2] = __float_as_uint(Qs[(rm + group)     * QS_ST + ks + tig + 4]);
            a[3] = __float_as_uint(Qs[(rm + group + 8) * QS_ST + ks + tig + 4]);
#pragma unroll
            for (int ni = 0; ni < 8; ni++) {
                uint32_t bb[2];
                bb[0] = __float_as_uint(KT[(ks + tig)     * KT_ST + ni * 8 + group]);
                bb[1] = __float_as_uint(KT[(ks + tig + 4) * KT_ST + ni * 8 + group]);
                mma_tf32(s[ni], a, bb);
            }
        }
        int row0 = qt0 + rm + group;
        bool diag = (jt == jt_max);
#pragma unroll
        for (int ni = 0; ni < 8; ni++) {
#pragma unroll
            for (int r = 0; r < 4; r++) s[ni][r] *= 0.125f;
            if (diag) {
                int c0 = j0 + ni * 8 + 2 * tig;
                if (c0     > row0)     s[ni][0] = -1e30f;
                if (c0 + 1 > row0)     s[ni][1] = -1e30f;
                if (c0     > row0 + 8) s[ni][2] = -1e30f;
                if (c0 + 1 > row0 + 8) s[ni][3] = -1e30f;
            }
        }
        float tm0 = -1e30f, tm1 = -1e30f;
#pragma unroll
        for (int ni = 0; ni < 8; ni++) {
            tm0 = fmaxf(tm0, fmaxf(s[ni][0], s[ni][1]));
            tm1 = fmaxf(tm1, fmaxf(s[ni][2], s[ni][3]));
        }
        tm0 = fmaxf(tm0, __shfl_xor_sync(0xffffffffu, tm0, 1));
        tm0 = fmaxf(tm0, __shfl_xor_sync(0xffffffffu, tm0, 2));
        tm1 = fmaxf(tm1, __shfl_xor_sync(0xffffffffu, tm1, 1));
        tm1 = fmaxf(tm1, __shfl_xor_sync(0xffffffffu, tm1, 2));
        float nm0 = fmaxf(m0, tm0), nm1 = fmaxf(m1, tm1);
        float f0 = __expf(m0 - nm0), f1 = __expf(m1 - nm1);
        float rs0 = 0.f, rs1 = 0.f;
#pragma unroll
        for (int ni = 0; ni < 8; ni++) {
            s[ni][0] = __expf(s[ni][0] - nm0);
            s[ni][1] = __expf(s[ni][1] - nm0);
            s[ni][2] = __expf(s[ni][2] - nm1);
            s[ni][3] = __expf(s[ni][3] - nm1);
            rs0 += s[ni][0] + s[ni][1];
            rs1 += s[ni][2] + s[ni][3];
        }
        rs0 += __shfl_xor_sync(0xffffffffu, rs0, 1);
        rs0 += __shfl_xor_sync(0xffffffffu, rs0, 2);
        rs1 += __shfl_xor_sync(0xffffffffu, rs1, 1);
        rs1 += __shfl_xor_sync(0xffffffffu, rs1, 2);
        l0 = l0 * f0 + rs0; l1 = l1 * f1 + rs1;
        m0 = nm0; m1 = nm1;
#pragma unroll
        for (int ni = 0; ni < 8; ni++) {
            o[ni][0] *= f0; o[ni][1] *= f0; o[ni][2] *= f1; o[ni][3] *= f1;
        }
#pragma unroll
        for (int ni = 0; ni < 8; ni++) {
            int c = ni * 8 + 2 * tig;
            Ps[(rm + group)     * PS_ST + c    ] = tf32r(s[ni][0]);
            Ps[(rm + group)     * PS_ST + c + 1] = tf32r(s[ni][1]);
            Ps[(rm + group + 8) * PS_ST + c    ] = tf32r(s[ni][2]);
            Ps[(rm + group + 8) * PS_ST + c + 1] = tf32r(s[ni][3]);
        }
        __syncwarp();
#pragma unroll
        for (int ks = 0; ks < 64; ks += 8) {
            uint32_t a[4];
            a[0] = __float_as_uint(Ps[(rm + group)     * PS_ST + ks + tig]);
            a[1] = __float_as_uint(Ps[(rm + group + 8) * PS_ST + ks + tig]);
            a[2] = __float_as_uint(Ps[(rm + group)     * PS_ST + ks + tig + 4]);
            a[3] = __float_as_uint(Ps[(rm + group + 8) * PS_ST + ks + tig + 4]);
#pragma unroll
            for (int ni = 0; ni < 8; ni++) {
                uint32_t bb[2];
                bb[0] = __float_as_uint(Vs[(ks + tig)     * VS_ST + ni * 8 + group]);
                bb[1] = __float_as_uint(Vs[(ks + tig + 4) * VS_ST + ni * 8 + group]);
                mma_tf32(o[ni], a, bb);
            }
        }
        __syncwarp();
    }

    float inv0 = 1.f / l0, inv1 = 1.f / l1;
    int r0 = qt0 + rm + group;
#pragma unroll
    for (int ni = 0; ni < 8; ni++) {
        int c = ni * 8 + 2 * tig;
        float2 w0 = make_float2(o[ni][0] * inv0, o[ni][1] * inv0);
        float2 w1 = make_float2(o[ni][2] * inv1, o[ni][3] * inv1);
        *(float2*)&out[(size_t)(b * SEQ + r0)     * DMODEL + h * 64 + c] = w0;
        *(float2*)&out[(size_t)(b * SEQ + r0 + 8) * DMODEL + h * 64 + c] = w1;
    }
}

// ---------------- swiglu elementwise (float4) --------------------------------
__global__ void swiglu_kernel(float4* __restrict__ u, const float4* __restrict__ v, int n4) {
    int i = blockIdx.x * blockDim.x + threadIdx.x;
    if (i < n4) {
        float4 a = u[i], b = v[i];
        a.x = a.x / (1.f + expf(-a.x)) * b.x;
        a.y = a.y / (1.f + expf(-a.y)) * b.y;
        a.z = a.z / (1.f + expf(-a.z)) * b.z;
        a.w = a.w / (1.f + expf(-a.w)) * b.w;
        u[i] = a;
    }
}

// ---------------- halt head --------------------------------------------------
__global__ void halt_kernel(const float* __restrict__ hh, const float* __restrict__ Wh2,
                            const float* __restrict__ bh2, const float* __restrict__ cum,
                            float* __restrict__ halt_out, float* __restrict__ cum_out) {
    int row = blockIdx.x;
    int t = threadIdx.x;
    float p = hh[(size_t)row * DHALT + t] * Wh2[t];
    for (int off = 16; off; off >>= 1) p += __shfl_xor_sync(0xffffffffu, p, off);
    __shared__ float red[8];
    if ((t & 31) == 0) red[t >> 5] = p;
    __syncthreads();
    if (t == 0) {
        float sum = red[0] + red[1] + red[2] + red[3] + red[4] + red[5] + red[6] + red[7] + bh2[0];
        float hp = 1.f / (1.f + expf(-sum));
        float c = cum[row];
        float still = (c < 0.99f) ? 1.f : 0.f;
        halt_out[row] = hp;
        cum_out[row] = c + hp * still;
    }
}

// ---------------- launch ------------------------------------------------------
extern "C" void kernel_launch(void* const* d_in, const int* in_sizes, int n_in,
                              void* d_out, int out_size) {
    const float* x    = (const float*)d_in[0];
    const float* cum  = (const float*)d_in[1];
    const float* g1   = (const float*)d_in[2];
    const float* g2   = (const float*)d_in[3];
    const float* Wqkv = (const float*)d_in[4];
    const float* Wo   = (const float*)d_in[5];
    const float* W1   = (const float*)d_in[6];
    const float* W2   = (const float*)d_in[7];
    const float* W3   = (const float*)d_in[8];
    const float* Wh1  = (const float*)d_in[9];
    const float* bh1  = (const float*)d_in[10];
    const float* Wh2  = (const float*)d_in[11];
    const float* bh2  = (const float*)d_in[12];

    float* outx = (float*)d_out;
    float* outh = outx + (size_t)NROWS * DMODEL;
    float* outc = outh + NROWS;

    float *h1, *qkvb, *attnb, *x1, *h2, *u, *v, *hhp;
    cudaGetSymbolAddress((void**)&h1,   g_h1);
    cudaGetSymbolAddress((void**)&qkvb, g_qkv);
    cudaGetSymbolAddress((void**)&attnb,g_attn);
    cudaGetSymbolAddress((void**)&x1,   g_x1);
    cudaGetSymbolAddress((void**)&h2,   g_h2);
    cudaGetSymbolAddress((void**)&u,    g_u);
    cudaGetSymbolAddress((void**)&v,    g_v);
    cudaGetSymbolAddress((void**)&hhp,  g_hh);

    cudaFuncSetAttribute(gemm_tc<0,1,1>, cudaFuncAttributeMaxDynamicSharedMemorySize, GEMM_SMEM);
    cudaFuncSetAttribute(gemm_tc<1,1,1>, cudaFuncAttributeMaxDynamicSharedMemorySize, GEMM_SMEM);
    cudaFuncSetAttribute(gemm_w1w2,      cudaFuncAttributeMaxDynamicSharedMemorySize, GEMM_SMEM);
    cudaFuncSetAttribute(gemm_tc<1,0,1>, cudaFuncAttributeMaxDynamicSharedMemorySize, GEMM_SMEM);
    cudaFuncSetAttribute(gemm_tc<2,1,1>, cudaFuncAttributeMaxDynamicSharedMemorySize, GEMM_SMEM);
    cudaFuncSetAttribute(attn_tc, cudaFuncAttributeMaxDynamicSharedMemorySize, ATTN_SMEM);

    // 1. h1 = rmsnorm(x, g1)
    rmsnorm_kernel<<<NROWS, 256>>>(x, g1, h1);
    // 2. qkv = h1 @ Wqkv
    gemm_tc<0,1,1><<<dim3(3 * DMODEL / 128, NROWS / 128), 256, GEMM_SMEM>>>(
        h1, Wqkv, qkvb, nullptr, NROWS, DMODEL, 3 * DMODEL);
    // 3. attention (heavy-first block order)
    attn_tc<<<dim3(NQT, BATCH * NHEAD), 128, ATTN_SMEM>>>(qkvb, attnb);
    // 4. x1 = x + attn @ Wo
    gemm_tc<1,1,1><<<dim3(DMODEL / 128, NROWS / 128), 256, GEMM_SMEM>>>(
        attnb, Wo, x1, x, NROWS, DMODEL, DMODEL);
    // 5. h2 = rmsnorm(x1, g2)
    rmsnorm_kernel<<<NROWS, 256>>>(x1, g2, h2);
    // 6. u = h2 @ W1 and v = h2 @ W2 in ONE launch
    {
        int ntile = (DFF + 127) / 128;   // 22
        gemm_w1w2<<<dim3(2 * ntile, NROWS / 128), 256, GEMM_SMEM>>>(
            h2, W1, W2, u, v, NROWS, DMODEL, DFF);
    }
    // 7. u = silu(u) * v
    {
        int n4 = NROWS * DFF / 4;
        swiglu_kernel<<<(n4 + 255) / 256, 256>>>((float4*)u, (const float4*)v, n4);
    }
    // 8. final x = x1 + u @ W3 -> d_out
    gemm_tc<1,0,1><<<dim3(DMODEL / 128, NROWS / 128), 256, GEMM_SMEM>>>(
        u, W3, outx, x1, NROWS, DFF, DMODEL);
    // 9. hh = gelu(x @ Wh1 + bh1)
    gemm_tc<2,1,1><<<dim3(DHALT / 128, NROWS / 128), 256, GEMM_SMEM>>>(
        outx, Wh1, hhp, bh1, NROWS, DMODEL, DHALT);
    // 10. halt probs + cum update
    halt_kernel<<<NROWS, 256>>>(hhp, Wh2, bh2, cum, outh, outc);
}

// round 14
// speedup vs baseline: 1.1682x; 1.1682x over previous
#include <cuda_runtime.h>
#include <math.h>
#include <stdint.h>

#define DMODEL 1024
#define NHEAD  16
#define HDIM   64
#define DFF    2730
#define DHALT  256
#define BATCH  2
#define SEQ    2048
#define NROWS  (BATCH*SEQ)   // 4096
#define NQT    (SEQ/64)      // 32 q-tiles per (b,h)

// ---------------- scratch (static device globals: allocation-guard safe) ---------
__device__ float g_h1[(size_t)NROWS*DMODEL];
__device__ float g_qkv[(size_t)NROWS*3*DMODEL];
__device__ float g_attn[(size_t)NROWS*DMODEL];
__device__ float g_x1[(size_t)NROWS*DMODEL];
__device__ float g_h2[(size_t)NROWS*DMODEL];
__device__ float g_u[(size_t)NROWS*DFF];
__device__ float g_v[(size_t)NROWS*DFF];
__device__ float g_hh[(size_t)NROWS*DHALT];

// ---------------- rmsnorm: one block per row --------------------------------
__global__ void rmsnorm_kernel(const float* __restrict__ x, const float* __restrict__ g,
                               float* __restrict__ y) {
    int row = blockIdx.x;
    const float* xr = x + (size_t)row * DMODEL;
    int t = threadIdx.x;
    float v[4];
    float ss = 0.f;
#pragma unroll
    for (int i = 0; i < 4; i++) { v[i] = xr[t + i * 256]; ss += v[i] * v[i]; }
    for (int off = 16; off; off >>= 1) ss += __shfl_xor_sync(0xffffffffu, ss, off);
    __shared__ float red[8];
    if ((t & 31) == 0) red[t >> 5] = ss;
    __syncthreads();
    if (t < 8) {
        float s2 = red[t];
        for (int off = 4; off; off >>= 1) s2 += __shfl_xor_sync(0xffu, s2, off);
        if (t == 0) red[0] = s2;
    }
    __syncthreads();
    float inv = rsqrtf(red[0] * (1.0f / DMODEL) + 1e-6f);
    float* yr = y + (size_t)row * DMODEL;
#pragma unroll
    for (int i = 0; i < 4; i++) {
        int c = t + i * 256;
        yr[c] = v[i] * inv * g[c];
    }
}

// ---------------- async-copy + mma helpers -----------------------------------
__device__ __forceinline__ uint32_t s2u(const void* p) {
    return (uint32_t)__cvta_generic_to_shared(p);
}
__device__ __forceinline__ void cp16(uint32_t d, const void* s) {
    asm volatile("cp.async.cg.shared.global [%0], [%1], 16;" :: "r"(d), "l"(s));
}
__device__ __forceinline__ void cp4(uint32_t d, const void* s) {
    asm volatile("cp.async.ca.shared.global [%0], [%1], 4;" :: "r"(d), "l"(s));
}
__device__ __forceinline__ void cp_commit() {
    asm volatile("cp.async.commit_group;");
}
__device__ __forceinline__ void mma_tf32(float c[4], const uint32_t a[4], const uint32_t b[2]) {
    asm volatile(
        "mma.sync.aligned.m16n8k8.row.col.f32.tf32.tf32.f32 "
        "{%0,%1,%2,%3}, {%4,%5,%6,%7}, {%8,%9}, {%0,%1,%2,%3};"
        : "+f"(c[0]), "+f"(c[1]), "+f"(c[2]), "+f"(c[3])
        : "r"(a[0]), "r"(a[1]), "r"(a[2]), "r"(a[3]), "r"(b[0]), "r"(b[1]));
}
__device__ __forceinline__ float tf32r(float x) {   // round-to-nearest tf32
    uint32_t y;
    asm("cvt.rna.tf32.f32 %0, %1;" : "=r"(y) : "f"(x));
    return __uint_as_float(y);
}

// ---------------- TF32 tensor-core GEMM (R9/R11 config: measured best) -------
#define AS_STRIDE 36
#define BS_STRIDE 136
#define A_TILE (128 * AS_STRIDE)
#define B_TILE (32 * BS_STRIDE)
#define STAGE  (A_TILE + B_TILE)
#define NSTAGE 3
#define GEMM_SMEM (NSTAGE * STAGE * sizeof(float))   // 107520 B

template <int MODE, int AVEC, int BVEC>
__global__ void __launch_bounds__(256) gemm_tc(const float* __restrict__ A,
                                               const float* __restrict__ Bm,
                                               float* __restrict__ C,
                                               const float* __restrict__ E,
                                               int M, int K, int N) {
    extern __shared__ float smem[];
    int tid = threadIdx.x;
    int w = tid >> 5, lane = tid & 31;
    int warpM = w >> 2, warpN = w & 3;
    int group = lane >> 2, tig = lane & 3;
    int m0 = blockIdx.y * 128, n0 = blockIdx.x * 128;

    auto load_tile = [&](int k0, int stg) {
        float* sA = smem + stg * STAGE;
        float* sB = sA + A_TILE;
        if (AVEC) {
#pragma unroll
            for (int i = 0; i < 4; i++) {
                int c = i * 256 + tid;
                int m = c >> 3, k4 = (c & 7) * 4;
                float* dp = sA + m * AS_STRIDE + k4;
                const float* sp = A + (size_t)(m0 + m) * K + k0 + k4;
                if (k0 + k4 + 4 <= K) cp16(s2u(dp), sp);
                else {
#pragma unroll
                    for (int e = 0; e < 4; e++) dp[e] = (k0 + k4 + e < K) ? sp[e] : 0.f;
                }
            }
        } else {
#pragma unroll
            for (int i = 0; i < 16; i++) {
                int c = i * 256 + tid;
                int m = c >> 5, kk = c & 31;
                float* dp = sA + m * AS_STRIDE + kk;
                if (k0 + kk < K) cp4(s2u(dp), A + (size_t)(m0 + m) * K + k0 + kk);
                else *dp = 0.f;
            }
        }
        if (BVEC) {
#pragma unroll
            for (int i = 0; i < 4; i++) {
                int c = i * 256 + tid;
                int kk = c >> 5, n4 = (c & 31) * 4;
                float* dp = sB + kk * BS_STRIDE + n4;
                if (k0 + kk < K) cp16(s2u(dp), Bm + (size_t)(k0 + kk) * N + n0 + n4);
                else { dp[0] = 0.f; dp[1] = 0.f; dp[2] = 0.f; dp[3] = 0.f; }
            }
        } else {
#pragma unroll
            for (int i = 0; i < 16; i++) {
                int c = i * 256 + tid;
                int kk = c >> 7, n = c & 127;
                float* dp = sB + kk * BS_STRIDE + n;
                if (k0 + kk < K && n0 + n < N) cp4(s2u(dp), Bm + (size_t)(k0 + kk) * N + n0 + n);
                else *dp = 0.f;
            }
        }
    };

    float acc[4][4][4];
#pragma unroll
    for (int mi = 0; mi < 4; mi++)
#pragma unroll
        for (int ni = 0; ni < 4; ni++)
#pragma unroll
            for (int r = 0; r < 4; r++) acc[mi][ni][r] = 0.f;

    int ntiles = (K + 31) / 32;
    load_tile(0, 0);
    cp_commit();
    if (ntiles > 1) { load_tile(32, 1); cp_commit(); }

    for (int t = 0; t < ntiles; t++) {
        if (t + 1 < ntiles) asm volatile("cp.async.wait_group 1;");
        else                asm volatile("cp.async.wait_group 0;");
        __syncthreads();
        if (t + 2 < ntiles) {
            load_tile((t + 2) * 32, (t + 2) % NSTAGE);
            cp_commit();
        }

        const float* sA = smem + (t % NSTAGE) * STAGE;
        const float* sB = sA + A_TILE;
#pragma unroll
        for (int ks = 0; ks < 32; ks += 8) {
            uint32_t afrag[4][4], bfrag[4][2];
#pragma unroll
            for (int mi = 0; mi < 4; mi++) {
                int rm = warpM * 64 + mi * 16;
                afrag[mi][0] = __float_as_uint(sA[(rm + group)     * AS_STRIDE + ks + tig]);
                afrag[mi][1] = __float_as_uint(sA[(rm + group + 8) * AS_STRIDE + ks + tig]);
                afrag[mi][2] = __float_as_uint(sA[(rm + group)     * AS_STRIDE + ks + tig + 4]);
                afrag[mi][3] = __float_as_uint(sA[(rm + group + 8) * AS_STRIDE + ks + tig + 4]);
            }
#pragma unroll
            for (int ni = 0; ni < 4; ni++) {
                int cn = warpN * 32 + ni * 8;
                bfrag[ni][0] = __float_as_uint(sB[(ks + tig)     * BS_STRIDE + cn + group]);
                bfrag[ni][1] = __float_as_uint(sB[(ks + tig + 4) * BS_STRIDE + cn + group]);
            }
#pragma unroll
            for (int mi = 0; mi < 4; mi++)
#pragma unroll
                for (int ni = 0; ni < 4; ni++)
                    mma_tf32(acc[mi][ni], afrag[mi], bfrag[ni]);
        }
    }

#pragma unroll
    for (int mi = 0; mi < 4; mi++) {
        int row = m0 + warpM * 64 + mi * 16 + group;
#pragma unroll
        for (int ni = 0; ni < 4; ni++) {
            int col = n0 + warpN * 32 + ni * 8 + tig * 2;
            if (col >= N) continue;
            float2 lo = make_float2(acc[mi][ni][0], acc[mi][ni][1]);
            float2 hi = make_float2(acc[mi][ni][2], acc[mi][ni][3]);
            if (MODE == 1) {
                float2 e0 = *(const float2*)&E[(size_t)row * N + col];
                float2 e1 = *(const float2*)&E[(size_t)(row + 8) * N + col];
                lo.x += e0.x; lo.y += e0.y; hi.x += e1.x; hi.y += e1.y;
            }
            if (MODE == 2) {
                float2 bb = *(const float2*)&E[col];
                lo.x += bb.x; lo.y += bb.y; hi.x += bb.x; hi.y += bb.y;
                lo.x = 0.5f * lo.x * (1.f + erff(lo.x * 0.70710678118654752f));
                lo.y = 0.5f * lo.y * (1.f + erff(lo.y * 0.70710678118654752f));
                hi.x = 0.5f * hi.x * (1.f + erff(hi.x * 0.70710678118654752f));
                hi.y = 0.5f * hi.y * (1.f + erff(hi.y * 0.70710678118654752f));
            }
            *(float2*)&C[(size_t)row * N + col] = lo;
            *(float2*)&C[(size_t)(row + 8) * N + col] = hi;
        }
    }
}

// ---------------- tf32 flash attention, KT store-conflict fixed --------------
// KT column swizzle: element (d, r) stored at column r ^ 8*((d>>2)&3) ^ 2*((d>>4)&3).
// Writes: 32 distinct banks per STS (was 16-way conflicted).
// Reads: XOR terms uniform per ks-step -> unchanged conflict-free pattern.
#define QS_ST 68
#define KT_ST 72
#define VS_ST 72
#define PS_ST 68
#define ATTN_SMEM ((64*QS_ST + 64*KT_ST + 64*VS_ST + 64*PS_ST) * 4)  // 71680 B

__global__ void __launch_bounds__(128) attn_tc(const float* __restrict__ qkv,
                                               float* __restrict__ out) {
    extern __shared__ float sm[];
    float* Qs = sm;
    float* KT = Qs + 64 * QS_ST;
    float* Vs = KT + 64 * KT_ST;
    float* Ps = Vs + 64 * VS_ST;
    int tid = threadIdx.x;
    int warp = tid >> 5, lane = tid & 31;
    int group = lane >> 2, tig = lane & 3;
    int bh = blockIdx.y;
    int b = bh >> 4, h = bh & 15;
    int qt0 = blockIdx.x * 64;
    size_t base = (size_t)b * SEQ * 3072;
    int rm = warp * 16;
    int ld_r = tid >> 4, ld_dq = tid & 15;
    // write-side swizzle: for all 4 head-dims d = ld_dq*4+c, (d>>2)&3 = ld_dq&3,
    // (d>>4)&3 = (ld_dq>>2)&3 -> one constant per thread
    int swt = (8 * (ld_dq & 3)) ^ (2 * ((ld_dq >> 2) & 3));

    // load Q tile (rna-rounded)
#pragma unroll
    for (int i = 0; i < 8; i++) {
        int e = i * 128 + tid;
        int r = e >> 4, dq = e & 15;
        float4 q = *(const float4*)&qkv[base + (size_t)(qt0 + r) * 3072 + h * 64 + dq * 4];
        float* d = &Qs[r * QS_ST + dq * 4];
        d[0] = tf32r(q.x); d[1] = tf32r(q.y); d[2] = tf32r(q.z); d[3] = tf32r(q.w);
    }

    float4 kreg[8], vreg[8];
    auto load_kv = [&](int j0) {
#pragma unroll
        for (int i = 0; i < 8; i++) {
            int r = ld_r + i * 8;
            const float* kp = &qkv[base + (size_t)(j0 + r) * 3072 + 1024 + h * 64 + ld_dq * 4];
            kreg[i] = *(const float4*)kp;
            vreg[i] = *(const float4*)(kp + 1024);
        }
    };

    float o[8][4];
    float m0 = -1e30f, m1 = -1e30f, l0 = 0.f, l1 = 0.f;
#pragma unroll
    for (int ni = 0; ni < 8; ni++)
#pragma unroll
        for (int r = 0; r < 4; r++) o[ni][r] = 0.f;

    int jt_max = blockIdx.x;
    load_kv(0);
    for (int jt = 0; jt <= jt_max; jt++) {
        __syncthreads();
        // dump staged regs -> smem (KT columns swizzled; conflict-free writes)
#pragma unroll
        for (int i = 0; i < 8; i++) {
            int r = ld_r + i * 8;
            int cs = r ^ swt;
            KT[(ld_dq * 4 + 0) * KT_ST + cs] = tf32r(kreg[i].x);
            KT[(ld_dq * 4 + 1) * KT_ST + cs] = tf32r(kreg[i].y);
            KT[(ld_dq * 4 + 2) * KT_ST + cs] = tf32r(kreg[i].z);
            KT[(ld_dq * 4 + 3) * KT_ST + cs] = tf32r(kreg[i].w);
            float4 vt;
            vt.x = tf32r(vreg[i].x); vt.y = tf32r(vreg[i].y);
            vt.z = tf32r(vreg[i].z); vt.w = tf32r(vreg[i].w);
            *(float4*)&Vs[r * VS_ST + ld_dq * 4] = vt;
        }
        __syncthreads();
        if (jt < jt_max) load_kv((jt + 1) * 64);

        int j0 = jt * 64;
        float s[8][4];
#pragma unroll
        for (int ni = 0; ni < 8; ni++)
#pragma unroll
            for (int r = 0; r < 4; r++) s[ni][r] = 0.f;
#pragma unroll
        for (int ks = 0; ks < 64; ks += 8) {
            // read-side swizzle constants (uniform across lanes per ks)
            int sw0 = (8 * ((ks >> 2) & 3)) ^ (2 * ((ks >> 4) & 3));
            int sw1 = (8 * (((ks >> 2) + 1) & 3)) ^ (2 * (((ks + 4) >> 4) & 3));
            uint32_t a[4];
            a[0] = __float_as_uint(Qs[(rm + group)     * QS_ST + ks + tig]);
            a[1] = __float_as_uint(Qs[(rm + group + 8) * QS_ST + ks + tig]);
            a[2] = __float_as_uint(Qs[(rm + group)     * QS_ST + ks + tig + 4]);
            a[3] = __float_as_uint(Qs[(rm + group + 8) * QS_ST + ks + tig + 4]);
#pragma unroll
            for (int ni = 0; ni < 8; ni++) {
                uint32_t bb[2];
                bb[0] = __float_as_uint(KT[(ks + tig)     * KT_ST + ((ni * 8 + group) ^ sw0)]);
                bb[1] = __float_as_uint(KT[(ks + tig + 4) * KT_ST + ((ni * 8 + group) ^ sw1)]);
                mma_tf32(s[ni], a, bb);
            }
        }
        int row0 = qt0 + rm + group;
        bool diag = (jt == jt_max);
#pragma unroll
        for (int ni = 0; ni < 8; ni++) {
#pragma unroll
            for (int r = 0; r < 4; r++) s[ni][r] *= 0.125f;
            if (diag) {
                int c0 = j0 + ni * 8 + 2 * tig;
                if (c0     > row0)     s[ni][0] = -1e30f;
                if (c0 + 1 > row0)     s[ni][1] = -1e30f;
                if (c0     > row0 + 8) s[ni][2] = -1e30f;
                if (c0 + 1 > row0 + 8) s[ni][3] = -1e30f;
            }
        }
        float tm0 = -1e30f, tm1 = -1e30f;
#pragma unroll
        for (int ni = 0; ni < 8; ni++) {
            tm0 = fmaxf(tm0, fmaxf(s[ni][0], s[ni][1]));
            tm1 = fmaxf(tm1, fmaxf(s[ni][2], s[ni][3]));
        }
        tm0 = fmaxf(tm0, __shfl_xor_sync(0xffffffffu, tm0, 1));
        tm0 = fmaxf(tm0, __shfl_xor_sync(0xffffffffu, tm0, 2));
        tm1 = fmaxf(tm1, __shfl_xor_sync(0xffffffffu, tm1, 1));
        tm1 = fmaxf(tm1, __shfl_xor_sync(0xffffffffu, tm1, 2));
        float nm0 = fmaxf(m0, tm0), nm1 = fmaxf(m1, tm1);
        float f0 = __expf(m0 - nm0), f1 = __expf(m1 - nm1);
        float rs0 = 0.f, rs1 = 0.f;
#pragma unroll
        for (int ni = 0; ni < 8; ni++) {
            s[ni][0] = __expf(s[ni][0] - nm0);
            s[ni][1] = __expf(s[ni][1] - nm0);
            s[ni][2] = __expf(s[ni][2] - nm1);
            s[ni][3] = __expf(s[ni][3] - nm1);
            rs0 += s[ni][0] + s[ni][1];
            rs1 += s[ni][2] + s[ni][3];
        }
        rs0 += __shfl_xor_sync(0xffffffffu, rs0, 1);
        rs0 += __shfl_xor_sync(0xffffffffu, rs0, 2);
        rs1 += __shfl_xor_sync(0xffffffffu, rs1, 1);
        rs1 += __shfl_xor_sync(0xffffffffu, rs1, 2);
        l0 = l0 * f0 + rs0; l1 = l1 * f1 + rs1;
        m0 = nm0; m1 = nm1;
#pragma unroll
        for (int ni = 0; ni < 8; ni++) {
            o[ni][0] *= f0; o[ni][1] *= f0; o[ni][2] *= f1; o[ni][3] *= f1;
        }
#pragma unroll
        for (int ni = 0; ni < 8; ni++) {
            int c = ni * 8 + 2 * tig;
            Ps[(rm + group)     * PS_ST + c    ] = tf32r(s[ni][0]);
            Ps[(rm + group)     * PS_ST + c + 1] = tf32r(s[ni][1]);
            Ps[(rm + group + 8) * PS_ST + c    ] = tf32r(s[ni][2]);
            Ps[(rm + group + 8) * PS_ST + c + 1] = tf32r(s[ni][3]);
        }
        __syncwarp();
#pragma unroll
        for (int ks = 0; ks < 64; ks += 8) {
            uint32_t a[4];
            a[0] = __float_as_uint(Ps[(rm + group)     * PS_ST + ks + tig]);
            a[1] = __float_as_uint(Ps[(rm + group + 8) * PS_ST + ks + tig]);
            a[2] = __float_as_uint(Ps[(rm + group)     * PS_ST + ks + tig + 4]);
            a[3] = __float_as_uint(Ps[(rm + group + 8) * PS_ST + ks + tig + 4]);
#pragma unroll
            for (int ni = 0; ni < 8; ni++) {
                uint32_t bb[2];
                bb[0] = __float_as_uint(Vs[(ks + tig)     * VS_ST + ni * 8 + group]);
                bb[1] = __float_as_uint(Vs[(ks + tig + 4) * VS_ST + ni * 8 + group]);
                mma_tf32(o[ni], a, bb);
            }
        }
        __syncwarp();
    }

    float inv0 = 1.f / l0, inv1 = 1.f / l1;
    int r0 = qt0 + rm + group;
#pragma unroll
    for (int ni = 0; ni < 8; ni++) {
        int c = ni * 8 + 2 * tig;
        float2 w0 = make_float2(o[ni][0] * inv0, o[ni][1] * inv0);
        float2 w1 = make_float2(o[ni][2] * inv1, o[ni][3] * inv1);
        *(float2*)&out[(size_t)(b * SEQ + r0)     * DMODEL + h * 64 + c] = w0;
        *(float2*)&out[(size_t)(b * SEQ + r0 + 8) * DMODEL + h * 64 + c] = w1;
    }
}

// ---------------- swiglu elementwise (float4) --------------------------------
__global__ void swiglu_kernel(float4* __restrict__ u, const float4* __restrict__ v, int n4) {
    int i = blockIdx.x * blockDim.x + threadIdx.x;
    if (i < n4) {
        float4 a = u[i], b = v[i];
        a.x = a.x / (1.f + expf(-a.x)) * b.x;
        a.y = a.y / (1.f + expf(-a.y)) * b.y;
        a.z = a.z / (1.f + expf(-a.z)) * b.z;
        a.w = a.w / (1.f + expf(-a.w)) * b.w;
        u[i] = a;
    }
}

// ---------------- halt head --------------------------------------------------
__global__ void halt_kernel(const float* __restrict__ hh, const float* __restrict__ Wh2,
                            const float* __restrict__ bh2, const float* __restrict__ cum,
                            float* __restrict__ halt_out, float* __restrict__ cum_out) {
    int row = blockIdx.x;
    int t = threadIdx.x;
    float p = hh[(size_t)row * DHALT + t] * Wh2[t];
    for (int off = 16; off; off >>= 1) p += __shfl_xor_sync(0xffffffffu, p, off);
    __shared__ float red[8];
    if ((t & 31) == 0) red[t >> 5] = p;
    __syncthreads();
    if (t == 0) {
        float sum = red[0] + red[1] + red[2] + red[3] + red[4] + red[5] + red[6] + red[7] + bh2[0];
        float hp = 1.f / (1.f + expf(-sum));
        float c = cum[row];
        float still = (c < 0.99f) ? 1.f : 0.f;
        halt_out[row] = hp;
        cum_out[row] = c + hp * still;
    }
}

// ---------------- launch ------------------------------------------------------
extern "C" void kernel_launch(void* const* d_in, const int* in_sizes, int n_in,
                              void* d_out, int out_size) {
    const float* x    = (const float*)d_in[0];
    const float* cum  = (const float*)d_in[1];
    const float* g1   = (const float*)d_in[2];
    const float* g2   = (const float*)d_in[3];
    const float* Wqkv = (const float*)d_in[4];
    const float* Wo   = (const float*)d_in[5];
    const float* W1   = (const float*)d_in[6];
    const float* W2   = (const float*)d_in[7];
    const float* W3   = (const float*)d_in[8];
    const float* Wh1  = (const float*)d_in[9];
    const float* bh1  = (const float*)d_in[10];
    const float* Wh2  = (const float*)d_in[11];
    const float* bh2  = (const float*)d_in[12];

    float* outx = (float*)d_out;
    float* outh = outx + (size_t)NROWS * DMODEL;
    float* outc = outh + NROWS;

    float *h1, *qkvb, *attnb, *x1, *h2, *u, *v, *hhp;
    cudaGetSymbolAddress((void**)&h1,   g_h1);
    cudaGetSymbolAddress((void**)&qkvb, g_qkv);
    cudaGetSymbolAddress((void**)&attnb,g_attn);
    cudaGetSymbolAddress((void**)&x1,   g_x1);
    cudaGetSymbolAddress((void**)&h2,   g_h2);
    cudaGetSymbolAddress((void**)&u,    g_u);
    cudaGetSymbolAddress((void**)&v,    g_v);
    cudaGetSymbolAddress((void**)&hhp,  g_hh);

    cudaFuncSetAttribute(gemm_tc<0,1,1>, cudaFuncAttributeMaxDynamicSharedMemorySize, GEMM_SMEM);
    cudaFuncSetAttribute(gemm_tc<1,1,1>, cudaFuncAttributeMaxDynamicSharedMemorySize, GEMM_SMEM);
    cudaFuncSetAttribute(gemm_tc<0,1,0>, cudaFuncAttributeMaxDynamicSharedMemorySize, GEMM_SMEM);
    cudaFuncSetAttribute(gemm_tc<1,0,1>, cudaFuncAttributeMaxDynamicSharedMemorySize, GEMM_SMEM);
    cudaFuncSetAttribute(gemm_tc<2,1,1>, cudaFuncAttributeMaxDynamicSharedMemorySize, GEMM_SMEM);
    cudaFuncSetAttribute(attn_tc, cudaFuncAttributeMaxDynamicSharedMemorySize, ATTN_SMEM);

    // 1. h1 = rmsnorm(x, g1)
    rmsnorm_kernel<<<NROWS, 256>>>(x, g1, h1);
    // 2. qkv = h1 @ Wqkv
    gemm_tc<0,1,1><<<dim3(3 * DMODEL / 128, NROWS / 128), 256, GEMM_SMEM>>>(
        h1, Wqkv, qkvb, nullptr, NROWS, DMODEL, 3 * DMODEL);
    // 3. attention (tf32 tensor cores, conflict-free KT transpose)
    attn_tc<<<dim3(NQT, BATCH * NHEAD), 128, ATTN_SMEM>>>(qkvb, attnb);
    // 4. x1 = x + attn @ Wo
    gemm_tc<1,1,1><<<dim3(DMODEL / 128, NROWS / 128), 256, GEMM_SMEM>>>(
        attnb, Wo, x1, x, NROWS, DMODEL, DMODEL);
    // 5. h2 = rmsnorm(x1, g2)
    rmsnorm_kernel<<<NROWS, 256>>>(x1, g2, h2);
    // 6. u = h2 @ W1, v = h2 @ W2  (separate launches: measured best)
    gemm_tc<0,1,0><<<dim3((DFF + 127) / 128, NROWS / 128), 256, GEMM_SMEM>>>(
        h2, W1, u, nullptr, NROWS, DMODEL, DFF);
    gemm_tc<0,1,0><<<dim3((DFF + 127) / 128, NROWS / 128), 256, GEMM_SMEM>>>(
        h2, W2, v, nullptr, NROWS, DMODEL, DFF);
    // 7. u = silu(u) * v
    {
        int n4 = NROWS * DFF / 4;
        swiglu_kernel<<<(n4 + 255) / 256, 256>>>((float4*)u, (const float4*)v, n4);
    }
    // 8. final x = x1 + u @ W3 -> d_out
    gemm_tc<1,0,1><<<dim3(DMODEL / 128, NROWS / 128), 256, GEMM_SMEM>>>(
        u, W3, outx, x1, NROWS, DFF, DMODEL);
    // 9. hh = gelu(x @ Wh1 + bh1)
    gemm_tc<2,1,1><<<dim3(DHALT / 128, NROWS / 128), 256, GEMM_SMEM>>>(
        outx, Wh1, hhp, bh1, NROWS, DMODEL, DHALT);
    // 10. halt probs + cum update
    halt_kernel<<<NROWS, 256>>>(hhp, Wh2, bh2, cum, outh, outc);
}